// round 8
// baseline (speedup 1.0000x reference)
#include <cuda_runtime.h>
#include <cuda_fp16.h>
#include <cstdint>
#include <math.h>

// Problem constants
#define BATCH 2
#define C 256
#define H 64
#define W 64
#define HW 4096
#define K2 9
#define CO 256
#define CK 2304        // C*K2
#define G 16           // channel groups for conv partial sums (16 ch each)

// Scratch (__device__ globals; allocation-free rule)
__device__ float  g_part[BATCH * G * 27 * HW];     // [b][g][o(27)][p]
__device__ __half g_vh[(size_t)BATCH * CK * HW];   // [b][ck][p]  p-contiguous fp16
__device__ __half g_wh[(size_t)CO * CK];           // W fp16, K-major rows of o

// ---------------------------------------------------------------------------
// helpers
// ---------------------------------------------------------------------------
__device__ __forceinline__ uint32_t smem_u32(const void* p) {
    uint32_t a;
    asm("{ .reg .u64 t; cvta.to.shared.u64 t, %1; cvt.u32.u64 %0, t; }" : "=r"(a) : "l"(p));
    return a;
}
__device__ __forceinline__ void cp_async16(uint32_t dst, const void* src) {
    asm volatile("cp.async.cg.shared.global [%0], [%1], 16;" :: "r"(dst), "l"(src));
}
#define CP_COMMIT() asm volatile("cp.async.commit_group;" ::: "memory")
#define CP_WAIT(n)  asm volatile("cp.async.wait_group %0;" :: "n"(n) : "memory")
#define SWZ128(off) ((off) ^ (((off) >> 3) & 0x70))

#define LDSM4(r, addr) \
    asm volatile("ldmatrix.sync.aligned.m8n8.x4.shared.b16 {%0,%1,%2,%3}, [%4];" \
        : "=r"((r)[0]), "=r"((r)[1]), "=r"((r)[2]), "=r"((r)[3]) : "r"(addr))
#define LDSM4T(r, addr) \
    asm volatile("ldmatrix.sync.aligned.m8n8.x4.trans.shared.b16 {%0,%1,%2,%3}, [%4];" \
        : "=r"((r)[0]), "=r"((r)[1]), "=r"((r)[2]), "=r"((r)[3]) : "r"(addr))

__device__ __forceinline__ void mma16816(float c[4], const uint32_t a[4], const uint32_t b[2]) {
    asm volatile(
        "mma.sync.aligned.m16n8k16.row.col.f32.f16.f16.f32 "
        "{%0,%1,%2,%3}, {%4,%5,%6,%7}, {%8,%9}, {%0,%1,%2,%3};"
        : "+f"(c[0]), "+f"(c[1]), "+f"(c[2]), "+f"(c[3])
        : "r"(a[0]), "r"(a[1]), "r"(a[2]), "r"(a[3]), "r"(b[0]), "r"(b[1]));
}

// ---------------------------------------------------------------------------
// Kernel 0: convert reg_w to fp16 (K-major rows of o)
// ---------------------------------------------------------------------------
__global__ __launch_bounds__(256)
void prep_w_kernel(const float* __restrict__ w)
{
    const int i = blockIdx.x * 256 + threadIdx.x;   // CO*CK/4 = 147456
    const float4 v = ((const float4*)w)[i];
    __half2* dst = (__half2*)(g_wh + (size_t)i * 4);
    dst[0] = __floats2half2_rn(v.x, v.y);
    dst[1] = __floats2half2_rn(v.z, v.w);
}

// ---------------------------------------------------------------------------
// Kernel 1: offset conv (18ch from residual) + mod conv (9ch from x).
// 4 pixels/thread, two passes, G=16 channel groups. 256 blocks x 128 thr.
// ---------------------------------------------------------------------------
__global__ __launch_bounds__(128)
void conv_offmod_kernel(const float* __restrict__ x,
                        const float* __restrict__ res,
                        const float* __restrict__ ow,   // [18][C][9]
                        const float* __restrict__ mw)   // [9][C][9]
{
    __shared__ __align__(16) float sw[16 * 27 * 12];

    const int tid  = threadIdx.x;
    const int bidx = blockIdx.x;          // B*G*8 = 256 blocks
    const int pblk = bidx & 7;
    const int g    = (bidx >> 3) & (G - 1);
    const int b    = bidx >> 7;
    const int p    = pblk * 512 + tid * 4;
    const int h    = p >> 6;
    const int w    = p & 63;

    const int cbase = g * 16;
    for (int i = tid; i < 16 * 243; i += 128) {
        const int ci = i / 243;
        const int t  = i % 243;
        const int c  = cbase + ci;
        const int o  = t / 9;
        const int tt = t % 9;
        float wv;
        if (o < 18) wv = ow[(size_t)o * CK + c * 9 + tt];
        else        wv = mw[(size_t)(o - 18) * CK + c * 9 + tt];
        sw[ci * 324 + o * 12 + tt] = wv;
    }
    __syncthreads();

    float* outp = g_part + (size_t)(b * G + g) * 27 * HW;

    // Pass A: 18 offset outputs from residual
    {
        float acc[18][4];
#pragma unroll
        for (int o = 0; o < 18; ++o)
#pragma unroll
            for (int j = 0; j < 4; ++j) acc[o][j] = 0.f;

        const float* rb = res + (size_t)b * C * HW;
        for (int ci = 0; ci < 16; ++ci) {
            const float* rc = rb + (size_t)(cbase + ci) * HW;
            float rv[18];
#pragma unroll
            for (int r = 0; r < 3; ++r) {
                const int hh = h + r - 1;
                const bool vy = ((unsigned)hh < 64u);
#pragma unroll
                for (int s = 0; s < 6; ++s) {
                    const int ww = w + s - 1;
                    const bool v = vy && ((unsigned)ww < 64u);
                    rv[r * 6 + s] = v ? rc[hh * 64 + ww] : 0.f;
                }
            }
            const float* swc = sw + ci * 324;
#pragma unroll
            for (int o = 0; o < 18; ++o) {
                const float4 wA = *(const float4*)(swc + o * 12);
                const float4 wB = *(const float4*)(swc + o * 12 + 4);
                const float  w8 = swc[o * 12 + 8];
#pragma unroll
                for (int j = 0; j < 4; ++j) {
                    acc[o][j] += wA.x * rv[j]      + wA.y * rv[j + 1]  + wA.z * rv[j + 2]
                               + wA.w * rv[j + 6]  + wB.x * rv[j + 7]  + wB.y * rv[j + 8]
                               + wB.z * rv[j + 12] + wB.w * rv[j + 13] + w8  * rv[j + 14];
                }
            }
        }
#pragma unroll
        for (int o = 0; o < 18; ++o) {
            float4 v; v.x = acc[o][0]; v.y = acc[o][1]; v.z = acc[o][2]; v.w = acc[o][3];
            *(float4*)(outp + o * HW + p) = v;
        }
    }

    // Pass B: 9 modulator outputs from x
    {
        float acc[9][4];
#pragma unroll
        for (int o = 0; o < 9; ++o)
#pragma unroll
            for (int j = 0; j < 4; ++j) acc[o][j] = 0.f;

        const float* xb = x + (size_t)b * C * HW;
        for (int ci = 0; ci < 16; ++ci) {
            const float* xc = xb + (size_t)(cbase + ci) * HW;
            float xv[18];
#pragma unroll
            for (int r = 0; r < 3; ++r) {
                const int hh = h + r - 1;
                const bool vy = ((unsigned)hh < 64u);
#pragma unroll
                for (int s = 0; s < 6; ++s) {
                    const int ww = w + s - 1;
                    const bool v = vy && ((unsigned)ww < 64u);
                    xv[r * 6 + s] = v ? xc[hh * 64 + ww] : 0.f;
                }
            }
            const float* swc = sw + ci * 324;
#pragma unroll
            for (int o = 0; o < 9; ++o) {
                const float4 wA = *(const float4*)(swc + (18 + o) * 12);
                const float4 wB = *(const float4*)(swc + (18 + o) * 12 + 4);
                const float  w8 = swc[(18 + o) * 12 + 8];
#pragma unroll
                for (int j = 0; j < 4; ++j) {
                    acc[o][j] += wA.x * xv[j]      + wA.y * xv[j + 1]  + wA.z * xv[j + 2]
                               + wA.w * xv[j + 6]  + wB.x * xv[j + 7]  + wB.y * xv[j + 8]
                               + wB.z * xv[j + 12] + wB.w * xv[j + 13] + w8  * xv[j + 14];
                }
            }
        }
#pragma unroll
        for (int o = 0; o < 9; ++o) {
            float4 v; v.x = acc[o][0]; v.y = acc[o][1]; v.z = acc[o][2]; v.w = acc[o][3];
            *(float4*)(outp + (18 + o) * HW + p) = v;
        }
    }
}

// ---------------------------------------------------------------------------
// Kernel 2: sampling. 288 threads: warp = tap k, lane = pixel; 2 pixel-tiles
// per thread; channels split 2-way across blockIdx.y -> 256 blocks.
// ---------------------------------------------------------------------------
__global__ __launch_bounds__(288)
void sample_kernel(const float* __restrict__ x,
                   const float* __restrict__ ob,   // [18]
                   const float* __restrict__ mb)   // [9]
{
    const int tid  = threadIdx.x;
    const int lane = tid & 31;
    const int k    = tid >> 5;           // 0..8
    const int chh  = blockIdx.y;         // channel half: 0 or 1
    const int b    = blockIdx.z;
    const int p0   = blockIdx.x * 64;

    int   l[2][4];
    float wq[2][4];

    const float* pb = g_part + (size_t)b * G * 27 * HW;
    const float kdy = (float)(k / 3 - 1);
    const float kdx = (float)(k % 3 - 1);

#pragma unroll
    for (int t = 0; t < 2; ++t) {
        const int p = p0 + t * 32 + lane;
        const int h = p >> 6;
        const int w = p & 63;

        float dy   = ob[2 * k];
        float dx   = ob[2 * k + 1];
        float mraw = mb[k];
#pragma unroll
        for (int g = 0; g < G; ++g) {
            dy   += pb[(g * 27 + 2 * k)     * HW + p];
            dx   += pb[(g * 27 + 2 * k + 1) * HW + p];
            mraw += pb[(g * 27 + 18 + k)    * HW + p];
        }
        const float m = 2.f / (1.f + expf(-mraw));

        const float py = dy + (float)h + kdy;
        const float px = dx + (float)w + kdx;
        const float y0f = floorf(py), x0f = floorf(px);
        const float wy1 = py - y0f,  wx1 = px - x0f;
        const float wy0 = 1.f - wy1, wx0 = 1.f - wx1;
        const int y0 = (int)y0f, x0 = (int)x0f;
        const int y1 = y0 + 1,   x1 = x0 + 1;

        bool v; int yc, xc;
        v = ((unsigned)y0 < 64u) && ((unsigned)x0 < 64u);
        yc = min(max(y0, 0), 63); xc = min(max(x0, 0), 63);
        l[t][0] = yc * 64 + xc; wq[t][0] = v ? wy0 * wx0 * m : 0.f;
        v = ((unsigned)y0 < 64u) && ((unsigned)x1 < 64u);
        yc = min(max(y0, 0), 63); xc = min(max(x1, 0), 63);
        l[t][1] = yc * 64 + xc; wq[t][1] = v ? wy0 * wx1 * m : 0.f;
        v = ((unsigned)y1 < 64u) && ((unsigned)x0 < 64u);
        yc = min(max(y1, 0), 63); xc = min(max(x0, 0), 63);
        l[t][2] = yc * 64 + xc; wq[t][2] = v ? wy1 * wx0 * m : 0.f;
        v = ((unsigned)y1 < 64u) && ((unsigned)x1 < 64u);
        yc = min(max(y1, 0), 63); xc = min(max(x1, 0), 63);
        l[t][3] = yc * 64 + xc; wq[t][3] = v ? wy1 * wx1 * m : 0.f;
    }

    const int c0 = chh * (C / 2);
    const float* xc = x + (size_t)b * C * HW + (size_t)c0 * HW;
    __half* dst0 = g_vh + ((size_t)b * CK + (size_t)c0 * 9 + k) * HW + p0 + lane;

#pragma unroll 4
    for (int c = 0; c < C / 2; ++c) {
        const float f0 = wq[0][0] * __ldg(xc + l[0][0]) + wq[0][1] * __ldg(xc + l[0][1])
                       + wq[0][2] * __ldg(xc + l[0][2]) + wq[0][3] * __ldg(xc + l[0][3]);
        const float f1 = wq[1][0] * __ldg(xc + l[1][0]) + wq[1][1] * __ldg(xc + l[1][1])
                       + wq[1][2] * __ldg(xc + l[1][2]) + wq[1][3] * __ldg(xc + l[1][3]);
        dst0[0]  = __float2half_rn(f0);
        dst0[32] = __float2half_rn(f1);
        xc   += HW;
        dst0 += (size_t)9 * HW;
    }
}

// ---------------------------------------------------------------------------
// Kernel 3: fp16 mma.sync GEMM, tile 128(o) x 64(p), BK=64, 3-stage cp.async
// + reg double buffering. 128 threads (4 warps: 2m x 2n, each 64x32).
// Grid 256 blocks -> 2-3 blocks/SM co-resident (cross-block latency hiding).
// A rows 128B SW128; B rows (64 halves) 128B SW128 + ldmatrix.trans.
// ---------------------------------------------------------------------------
#define BKH    64
#define ATILEB 16384                     // 128 rows * 128 B
#define BTILEB 8192                      // 64 k-rows * 128 B
#define STAGEB (ATILEB + BTILEB)         // 24 KB
#define NSTAGE 3
#define NCH    (CK / BKH)                // 36
#define GEMM_SMEM (NSTAGE * STAGEB)      // 73728 B

__global__ __launch_bounds__(128)
void gemm_mma_kernel(float* __restrict__ out)
{
    extern __shared__ char smc[];
    const uint32_t sb = smem_u32(smc);

    const int tid  = threadIdx.x;
    const int lane = tid & 31;
    const int wid  = tid >> 5;
    const int b    = blockIdx.z;
    const int m0   = blockIdx.y * 128;   // o
    const int n0   = blockIdx.x * 64;    // p

    const __half* gA = g_wh + (size_t)m0 * CK;
    const __half* gB = g_vh + (size_t)b * CK * HW + n0;

    // ---- A loader: thread t -> row t, 8x16B chunks, SW128 ----
    const __half* pa = gA + (size_t)tid * CK;
    uint32_t aswo[8];
#pragma unroll
    for (int j = 0; j < 8; ++j)
        aswo[j] = SWZ128((uint32_t)(tid * 128 + j * 16));

    // ---- B loader: k-row = t>>1 (0..63), 4x16B cols, SW128 ----
    const int brr = tid >> 1;
    const int bseg = tid & 1;
    const __half* pv = gB + (size_t)brr * HW + bseg * 32;
    uint32_t bswo[4];
#pragma unroll
    for (int j = 0; j < 4; ++j)
        bswo[j] = ATILEB + SWZ128((uint32_t)(brr * 128 + (bseg * 4 + j) * 16));

#define LOAD_TILE(stage, ch) do {                                             \
        const uint32_t _s = sb + (stage) * STAGEB;                            \
        const __half* _pa = pa + (size_t)(ch) * BKH;                          \
        cp_async16(_s + aswo[0], _pa);                                        \
        cp_async16(_s + aswo[1], _pa + 8);                                    \
        cp_async16(_s + aswo[2], _pa + 16);                                   \
        cp_async16(_s + aswo[3], _pa + 24);                                   \
        cp_async16(_s + aswo[4], _pa + 32);                                   \
        cp_async16(_s + aswo[5], _pa + 40);                                   \
        cp_async16(_s + aswo[6], _pa + 48);                                   \
        cp_async16(_s + aswo[7], _pa + 56);                                   \
        const __half* _pv = pv + (size_t)(ch) * BKH * HW;                     \
        cp_async16(_s + bswo[0], _pv);                                        \
        cp_async16(_s + bswo[1], _pv + 8);                                    \
        cp_async16(_s + bswo[2], _pv + 16);                                   \
        cp_async16(_s + bswo[3], _pv + 24);                                   \
    } while (0)

    // ---- ldmatrix offsets ----
    const int wm = (wid >> 1) * 64;      // warp m (o): 0 / 64
    const int wn = (wid & 1) * 32;       // warp n (p): 0 / 32
    uint32_t aOff[4];
#pragma unroll
    for (int mt = 0; mt < 4; ++mt) {
        const uint32_t off = (uint32_t)((wm + mt * 16 + (lane & 15)) * 128
                                        + ((lane & 16) ? 16 : 0));
        aOff[mt] = SWZ128(off);
    }
    // B trans frags: koff = k row 0..15 within step; 16B col cc = n/8
    const int mIdx = lane >> 3;
    const int koff = ((mIdx & 1) << 3) + (lane & 7);
    const int cc0  = (wn >> 3) + (mIdx >> 1);   // first LDSM: n wn..wn+15
    const int cc1  = cc0 + 2;                   // second LDSM: n wn+16..wn+31
    const uint32_t bO0 = ATILEB + SWZ128((uint32_t)(koff * 128 + cc0 * 16));
    const uint32_t bO1 = ATILEB + SWZ128((uint32_t)(koff * 128 + cc1 * 16));

#define LOAD_FRAGS(buf, sbase, s) do {                                        \
        LDSM4(afr[buf][0], (sbase) + (aOff[0] ^ ((s) << 5)));                 \
        LDSM4(afr[buf][1], (sbase) + (aOff[1] ^ ((s) << 5)));                 \
        LDSM4(afr[buf][2], (sbase) + (aOff[2] ^ ((s) << 5)));                 \
        LDSM4(afr[buf][3], (sbase) + (aOff[3] ^ ((s) << 5)));                 \
        LDSM4T(b0f[buf], (sbase) + bO0 + (s) * 2048);                         \
        LDSM4T(b1f[buf], (sbase) + bO1 + (s) * 2048);                         \
    } while (0)

    float c[16][4];
#pragma unroll
    for (int i = 0; i < 16; ++i)
#pragma unroll
        for (int j = 0; j < 4; ++j) c[i][j] = 0.f;

    uint32_t afr[2][4][4], b0f[2][4], b1f[2][4];

    LOAD_TILE(0, 0); CP_COMMIT();
    LOAD_TILE(1, 1); CP_COMMIT();

    int stage = 0;
    for (int ch = 0; ch < NCH; ++ch) {
        if (ch + 2 < NCH) {
            const int ns = (stage + 2 >= NSTAGE) ? stage + 2 - NSTAGE : stage + 2;
            LOAD_TILE(ns, ch + 2);
        }
        CP_COMMIT();
        CP_WAIT(2);
        __syncthreads();

        const uint32_t sbase = sb + stage * STAGEB;
        LOAD_FRAGS(0, sbase, 0);
#pragma unroll
        for (int s = 0; s < 4; ++s) {
            const int cur = s & 1;
            if (s < 3) LOAD_FRAGS(cur ^ 1, sbase, s + 1);
#pragma unroll
            for (int mt = 0; mt < 4; ++mt) {
                mma16816(c[mt * 4 + 0], afr[cur][mt], &b0f[cur][0]);
                mma16816(c[mt * 4 + 1], afr[cur][mt], &b0f[cur][2]);
                mma16816(c[mt * 4 + 2], afr[cur][mt], &b1f[cur][0]);
                mma16816(c[mt * 4 + 3], afr[cur][mt], &b1f[cur][2]);
            }
        }
        __syncthreads();
        stage = (stage + 1 >= NSTAGE) ? 0 : stage + 1;
    }

    // epilogue
    const int qr = lane >> 2;
    const int qc = lane & 3;
#pragma unroll
    for (int mt = 0; mt < 4; ++mt) {
#pragma unroll
        for (int nt = 0; nt < 4; ++nt) {
            const int o = m0 + wm + mt * 16 + qr;
            const int p = n0 + wn + nt * 8 + 2 * qc;
            float* o0 = out + ((size_t)(b * CO + o)) * HW + p;
            float2 v0; v0.x = c[mt * 4 + nt][0]; v0.y = c[mt * 4 + nt][1];
            *(float2*)o0 = v0;
            float2 v1; v1.x = c[mt * 4 + nt][2]; v1.y = c[mt * 4 + nt][3];
            *(float2*)(o0 + 8 * HW) = v1;
        }
    }
}

// ---------------------------------------------------------------------------
extern "C" void kernel_launch(void* const* d_in, const int* in_sizes, int n_in,
                              void* d_out, int out_size)
{
    const float* x   = (const float*)d_in[0];   // [2,256,64,64]
    const float* res = (const float*)d_in[1];   // [2,256,64,64]
    const float* ow  = (const float*)d_in[2];   // [18,256,3,3]
    const float* ob  = (const float*)d_in[3];   // [18]
    const float* mw  = (const float*)d_in[4];   // [9,256,3,3]
    const float* mb  = (const float*)d_in[5];   // [9]
    const float* rw  = (const float*)d_in[6];   // [256,256,3,3]
    float* out = (float*)d_out;                 // [2,256,64,64]

    static int smem_set = 0;
    if (!smem_set) {
        cudaFuncSetAttribute(gemm_mma_kernel,
                             cudaFuncAttributeMaxDynamicSharedMemorySize, GEMM_SMEM);
        smem_set = 1;
    }

    prep_w_kernel<<<CO * CK / 4 / 256, 256>>>(rw);
    conv_offmod_kernel<<<256, 128>>>(x, res, ow, mw);
    sample_kernel<<<dim3(HW / 64, 2, BATCH), 288>>>(x, ob, mb);
    gemm_mma_kernel<<<dim3(HW / 64, CO / 128, BATCH), 128, GEMM_SMEM>>>(out);
}

// round 9
// speedup vs baseline: 1.2198x; 1.2198x over previous
#include <cuda_runtime.h>
#include <cuda_fp16.h>
#include <cstdint>
#include <math.h>

// Problem constants
#define BATCH 2
#define C 256
#define H 64
#define W 64
#define HW 4096
#define K2 9
#define CO 256
#define CK 2304        // C*K2
#define G 16           // channel groups for conv partial sums (16 ch each)

// Scratch (__device__ globals; allocation-free rule)
__device__ float  g_part[BATCH * G * 27 * HW];     // [b][g][o(27)][p]
__device__ __half g_vh[(size_t)BATCH * CK * HW];   // [b][ck][p]  p-contiguous fp16
__device__ __half g_wh[(size_t)CO * CK];           // W fp16, K-major rows of o
__device__ float  g_po[(size_t)BATCH * CO * HW];   // split-K partial output

// ---------------------------------------------------------------------------
// helpers
// ---------------------------------------------------------------------------
__device__ __forceinline__ uint32_t smem_u32(const void* p) {
    uint32_t a;
    asm("{ .reg .u64 t; cvta.to.shared.u64 t, %1; cvt.u32.u64 %0, t; }" : "=r"(a) : "l"(p));
    return a;
}
__device__ __forceinline__ void cp_async16(uint32_t dst, const void* src) {
    asm volatile("cp.async.cg.shared.global [%0], [%1], 16;" :: "r"(dst), "l"(src));
}
#define CP_COMMIT() asm volatile("cp.async.commit_group;" ::: "memory")
#define CP_WAIT(n)  asm volatile("cp.async.wait_group %0;" :: "n"(n) : "memory")
#define SWZ128(off) ((off) ^ (((off) >> 3) & 0x70))

#define LDSM4(r, addr) \
    asm volatile("ldmatrix.sync.aligned.m8n8.x4.shared.b16 {%0,%1,%2,%3}, [%4];" \
        : "=r"((r)[0]), "=r"((r)[1]), "=r"((r)[2]), "=r"((r)[3]) : "r"(addr))
#define LDSM4T(r, addr) \
    asm volatile("ldmatrix.sync.aligned.m8n8.x4.trans.shared.b16 {%0,%1,%2,%3}, [%4];" \
        : "=r"((r)[0]), "=r"((r)[1]), "=r"((r)[2]), "=r"((r)[3]) : "r"(addr))

__device__ __forceinline__ void mma16816(float c[4], const uint32_t a[4], const uint32_t b[2]) {
    asm volatile(
        "mma.sync.aligned.m16n8k16.row.col.f32.f16.f16.f32 "
        "{%0,%1,%2,%3}, {%4,%5,%6,%7}, {%8,%9}, {%0,%1,%2,%3};"
        : "+f"(c[0]), "+f"(c[1]), "+f"(c[2]), "+f"(c[3])
        : "r"(a[0]), "r"(a[1]), "r"(a[2]), "r"(a[3]), "r"(b[0]), "r"(b[1]));
}

// ---------------------------------------------------------------------------
// Kernel 1: offset conv (18ch from res) + mod conv (9ch from x), 4 px/thread,
// two passes, G=16 groups. Blocks 0..255 = conv; blocks 256..399 = W->fp16.
// ---------------------------------------------------------------------------
__global__ __launch_bounds__(128)
void conv_offmod_kernel(const float* __restrict__ x,
                        const float* __restrict__ res,
                        const float* __restrict__ ow,   // [18][C][9]
                        const float* __restrict__ mw,   // [9][C][9]
                        const float* __restrict__ rw)   // [256][C][9]
{
    __shared__ __align__(16) float sw[16 * 27 * 12];

    const int tid  = threadIdx.x;
    const int bidx = blockIdx.x;

    if (bidx >= 256) {
        // fused prep_w: convert reg_w to fp16
        const int n4 = CO * CK / 4;                // 147456 float4
        for (int i = (bidx - 256) * 128 + tid; i < n4; i += 144 * 128) {
            const float4 v = ((const float4*)rw)[i];
            __half2* dst = (__half2*)(g_wh + (size_t)i * 4);
            dst[0] = __floats2half2_rn(v.x, v.y);
            dst[1] = __floats2half2_rn(v.z, v.w);
        }
        return;
    }

    const int pblk = bidx & 7;
    const int g    = (bidx >> 3) & (G - 1);
    const int b    = bidx >> 7;
    const int p    = pblk * 512 + tid * 4;
    const int h    = p >> 6;
    const int w    = p & 63;

    const int cbase = g * 16;
    for (int i = tid; i < 16 * 243; i += 128) {
        const int ci = i / 243;
        const int t  = i % 243;
        const int c  = cbase + ci;
        const int o  = t / 9;
        const int tt = t % 9;
        float wv;
        if (o < 18) wv = ow[(size_t)o * CK + c * 9 + tt];
        else        wv = mw[(size_t)(o - 18) * CK + c * 9 + tt];
        sw[ci * 324 + o * 12 + tt] = wv;
    }
    __syncthreads();

    float* outp = g_part + (size_t)(b * G + g) * 27 * HW;

    // Pass A: 18 offset outputs from residual
    {
        float acc[18][4];
#pragma unroll
        for (int o = 0; o < 18; ++o)
#pragma unroll
            for (int j = 0; j < 4; ++j) acc[o][j] = 0.f;

        const float* rb = res + (size_t)b * C * HW;
        for (int ci = 0; ci < 16; ++ci) {
            const float* rc = rb + (size_t)(cbase + ci) * HW;
            float rv[18];
#pragma unroll
            for (int r = 0; r < 3; ++r) {
                const int hh = h + r - 1;
                const bool vy = ((unsigned)hh < 64u);
#pragma unroll
                for (int s = 0; s < 6; ++s) {
                    const int ww = w + s - 1;
                    const bool v = vy && ((unsigned)ww < 64u);
                    rv[r * 6 + s] = v ? rc[hh * 64 + ww] : 0.f;
                }
            }
            const float* swc = sw + ci * 324;
#pragma unroll
            for (int o = 0; o < 18; ++o) {
                const float4 wA = *(const float4*)(swc + o * 12);
                const float4 wB = *(const float4*)(swc + o * 12 + 4);
                const float  w8 = swc[o * 12 + 8];
#pragma unroll
                for (int j = 0; j < 4; ++j) {
                    acc[o][j] += wA.x * rv[j]      + wA.y * rv[j + 1]  + wA.z * rv[j + 2]
                               + wA.w * rv[j + 6]  + wB.x * rv[j + 7]  + wB.y * rv[j + 8]
                               + wB.z * rv[j + 12] + wB.w * rv[j + 13] + w8  * rv[j + 14];
                }
            }
        }
#pragma unroll
        for (int o = 0; o < 18; ++o) {
            float4 v; v.x = acc[o][0]; v.y = acc[o][1]; v.z = acc[o][2]; v.w = acc[o][3];
            *(float4*)(outp + o * HW + p) = v;
        }
    }

    // Pass B: 9 modulator outputs from x
    {
        float acc[9][4];
#pragma unroll
        for (int o = 0; o < 9; ++o)
#pragma unroll
            for (int j = 0; j < 4; ++j) acc[o][j] = 0.f;

        const float* xb = x + (size_t)b * C * HW;
        for (int ci = 0; ci < 16; ++ci) {
            const float* xc = xb + (size_t)(cbase + ci) * HW;
            float xv[18];
#pragma unroll
            for (int r = 0; r < 3; ++r) {
                const int hh = h + r - 1;
                const bool vy = ((unsigned)hh < 64u);
#pragma unroll
                for (int s = 0; s < 6; ++s) {
                    const int ww = w + s - 1;
                    const bool v = vy && ((unsigned)ww < 64u);
                    xv[r * 6 + s] = v ? xc[hh * 64 + ww] : 0.f;
                }
            }
            const float* swc = sw + ci * 324;
#pragma unroll
            for (int o = 0; o < 9; ++o) {
                const float4 wA = *(const float4*)(swc + (18 + o) * 12);
                const float4 wB = *(const float4*)(swc + (18 + o) * 12 + 4);
                const float  w8 = swc[(18 + o) * 12 + 8];
#pragma unroll
                for (int j = 0; j < 4; ++j) {
                    acc[o][j] += wA.x * xv[j]      + wA.y * xv[j + 1]  + wA.z * xv[j + 2]
                               + wA.w * xv[j + 6]  + wB.x * xv[j + 7]  + wB.y * xv[j + 8]
                               + wB.z * xv[j + 12] + wB.w * xv[j + 13] + w8  * xv[j + 14];
                }
            }
        }
#pragma unroll
        for (int o = 0; o < 9; ++o) {
            float4 v; v.x = acc[o][0]; v.y = acc[o][1]; v.z = acc[o][2]; v.w = acc[o][3];
            *(float4*)(outp + (18 + o) * HW + p) = v;
        }
    }
}

// ---------------------------------------------------------------------------
// Kernel 2: sampling (R7 config: warp = tap k, 2 pixel-tiles/thread,
// channels split 2-way across blockIdx.y).
// ---------------------------------------------------------------------------
__global__ __launch_bounds__(288)
void sample_kernel(const float* __restrict__ x,
                   const float* __restrict__ ob,   // [18]
                   const float* __restrict__ mb)   // [9]
{
    const int tid  = threadIdx.x;
    const int lane = tid & 31;
    const int k    = tid >> 5;           // 0..8
    const int chh  = blockIdx.y;         // channel half
    const int b    = blockIdx.z;
    const int p0   = blockIdx.x * 64;

    int   l[2][4];
    float wq[2][4];

    const float* pb = g_part + (size_t)b * G * 27 * HW;
    const float kdy = (float)(k / 3 - 1);
    const float kdx = (float)(k % 3 - 1);

#pragma unroll
    for (int t = 0; t < 2; ++t) {
        const int p = p0 + t * 32 + lane;
        const int h = p >> 6;
        const int w = p & 63;

        float dy   = ob[2 * k];
        float dx   = ob[2 * k + 1];
        float mraw = mb[k];
#pragma unroll
        for (int g = 0; g < G; ++g) {
            dy   += pb[(g * 27 + 2 * k)     * HW + p];
            dx   += pb[(g * 27 + 2 * k + 1) * HW + p];
            mraw += pb[(g * 27 + 18 + k)    * HW + p];
        }
        const float m = 2.f / (1.f + expf(-mraw));

        const float py = dy + (float)h + kdy;
        const float px = dx + (float)w + kdx;
        const float y0f = floorf(py), x0f = floorf(px);
        const float wy1 = py - y0f,  wx1 = px - x0f;
        const float wy0 = 1.f - wy1, wx0 = 1.f - wx1;
        const int y0 = (int)y0f, x0 = (int)x0f;
        const int y1 = y0 + 1,   x1 = x0 + 1;

        bool v; int yc, xc;
        v = ((unsigned)y0 < 64u) && ((unsigned)x0 < 64u);
        yc = min(max(y0, 0), 63); xc = min(max(x0, 0), 63);
        l[t][0] = yc * 64 + xc; wq[t][0] = v ? wy0 * wx0 * m : 0.f;
        v = ((unsigned)y0 < 64u) && ((unsigned)x1 < 64u);
        yc = min(max(y0, 0), 63); xc = min(max(x1, 0), 63);
        l[t][1] = yc * 64 + xc; wq[t][1] = v ? wy0 * wx1 * m : 0.f;
        v = ((unsigned)y1 < 64u) && ((unsigned)x0 < 64u);
        yc = min(max(y1, 0), 63); xc = min(max(x0, 0), 63);
        l[t][2] = yc * 64 + xc; wq[t][2] = v ? wy1 * wx0 * m : 0.f;
        v = ((unsigned)y1 < 64u) && ((unsigned)x1 < 64u);
        yc = min(max(y1, 0), 63); xc = min(max(x1, 0), 63);
        l[t][3] = yc * 64 + xc; wq[t][3] = v ? wy1 * wx1 * m : 0.f;
    }

    const int c0 = chh * (C / 2);
    const float* xc = x + (size_t)b * C * HW + (size_t)c0 * HW;
    __half* dst0 = g_vh + ((size_t)b * CK + (size_t)c0 * 9 + k) * HW + p0 + lane;

#pragma unroll 4
    for (int c = 0; c < C / 2; ++c) {
        const float f0 = wq[0][0] * __ldg(xc + l[0][0]) + wq[0][1] * __ldg(xc + l[0][1])
                       + wq[0][2] * __ldg(xc + l[0][2]) + wq[0][3] * __ldg(xc + l[0][3]);
        const float f1 = wq[1][0] * __ldg(xc + l[1][0]) + wq[1][1] * __ldg(xc + l[1][1])
                       + wq[1][2] * __ldg(xc + l[1][2]) + wq[1][3] * __ldg(xc + l[1][3]);
        dst0[0]  = __float2half_rn(f0);
        dst0[32] = __float2half_rn(f1);
        xc   += HW;
        dst0 += (size_t)9 * HW;
    }
}

// ---------------------------------------------------------------------------
// Kernel 3: fp16 mma.sync GEMM, split-K by 2. Tile 128x128, BK=64, 3-stage
// cp.async, 8 warps (2m x 4n, each 64x32), NO reg double-buffer (124 regs).
// blockIdx.z = b*2 + kh; kh=0 -> out, kh=1 -> g_po. Grid 256 blocks, 2/SM.
// ---------------------------------------------------------------------------
#define BKH    64
#define ATILEB 16384
#define BTILEB 16384
#define STAGEB (ATILEB + BTILEB)
#define NSTAGE 3
#define NCHH   18                        // chunks per K-half
#define GEMM_SMEM (NSTAGE * STAGEB)      // 98304 B

__global__ __launch_bounds__(256, 2)
void gemm_mma_kernel(float* __restrict__ out)
{
    extern __shared__ char smc[];
    const uint32_t sb = smem_u32(smc);

    const int tid  = threadIdx.x;
    const int lane = tid & 31;
    const int wid  = tid >> 5;
    const int bz   = blockIdx.z;
    const int b    = bz >> 1;
    const int kh   = bz & 1;
    const int m0   = blockIdx.y * 128;   // o
    const int n0   = blockIdx.x * 128;   // p

    const __half* gA = g_wh + (size_t)m0 * CK + (size_t)kh * NCHH * BKH;
    const __half* gB = g_vh + (size_t)b * CK * HW + (size_t)kh * NCHH * BKH * HW + n0;

    const int ar  = tid >> 1;
    const int seg = tid & 1;
    const __half* pa = gA + (size_t)ar * CK + seg * 32;
    uint32_t aswo[4];
#pragma unroll
    for (int j = 0; j < 4; ++j)
        aswo[j] = SWZ128((uint32_t)(ar * 128 + seg * 64 + j * 16));

    const int br = tid >> 2;
    const int cg = tid & 3;
    const __half* pv = gB + (size_t)br * HW + cg * 32;
    uint32_t bswo[4];
#pragma unroll
    for (int j = 0; j < 4; ++j) {
        const int cc = cg * 4 + j;
        bswo[j] = ATILEB + (uint32_t)br * 256 + ((uint32_t)(cc ^ (br & 7)) << 4);
    }

#define LOAD_TILE(stage, ch) do {                                             \
        const uint32_t _s = sb + (stage) * STAGEB;                            \
        const __half* _pa = pa + (size_t)(ch) * BKH;                          \
        cp_async16(_s + aswo[0], _pa);                                        \
        cp_async16(_s + aswo[1], _pa + 8);                                    \
        cp_async16(_s + aswo[2], _pa + 16);                                   \
        cp_async16(_s + aswo[3], _pa + 24);                                   \
        const __half* _pv = pv + (size_t)(ch) * BKH * HW;                     \
        cp_async16(_s + bswo[0], _pv);                                        \
        cp_async16(_s + bswo[1], _pv + 8);                                    \
        cp_async16(_s + bswo[2], _pv + 16);                                   \
        cp_async16(_s + bswo[3], _pv + 24);                                   \
    } while (0)

    const int wm = (wid >> 2) * 64;
    const int wn = (wid & 3) * 32;
    uint32_t aOff[4];
#pragma unroll
    for (int mt = 0; mt < 4; ++mt) {
        const uint32_t off = (uint32_t)((wm + mt * 16 + (lane & 15)) * 128
                                        + ((lane & 16) ? 16 : 0));
        aOff[mt] = SWZ128(off);
    }
    const int mIdx = lane >> 3;
    const int koff = ((mIdx & 1) << 3) + (lane & 7);
    const int cc0  = (wn >> 3) + (mIdx >> 1);
    const int cc1  = cc0 + 2;
    const uint32_t bO0 = ATILEB + (uint32_t)koff * 256 + ((uint32_t)(cc0 ^ (koff & 7)) << 4);
    const uint32_t bO1 = ATILEB + (uint32_t)koff * 256 + ((uint32_t)(cc1 ^ (koff & 7)) << 4);

    float c[16][4];
#pragma unroll
    for (int i = 0; i < 16; ++i)
#pragma unroll
        for (int j = 0; j < 4; ++j) c[i][j] = 0.f;

    LOAD_TILE(0, 0); CP_COMMIT();
    LOAD_TILE(1, 1); CP_COMMIT();

    int stage = 0;
    for (int ch = 0; ch < NCHH; ++ch) {
        if (ch + 2 < NCHH) {
            const int ns = (stage + 2 >= NSTAGE) ? stage + 2 - NSTAGE : stage + 2;
            LOAD_TILE(ns, ch + 2);
        }
        CP_COMMIT();
        CP_WAIT(2);
        __syncthreads();

        const uint32_t sbase = sb + stage * STAGEB;
#pragma unroll
        for (int s = 0; s < 4; ++s) {
            uint32_t a[4][4], b0[4], b1[4];
#pragma unroll
            for (int mt = 0; mt < 4; ++mt)
                LDSM4(a[mt], sbase + (aOff[mt] ^ (s << 5)));
            LDSM4T(b0, sbase + bO0 + s * 4096);
            LDSM4T(b1, sbase + bO1 + s * 4096);
#pragma unroll
            for (int mt = 0; mt < 4; ++mt) {
                mma16816(c[mt * 4 + 0], a[mt], &b0[0]);
                mma16816(c[mt * 4 + 1], a[mt], &b0[2]);
                mma16816(c[mt * 4 + 2], a[mt], &b1[0]);
                mma16816(c[mt * 4 + 3], a[mt], &b1[2]);
            }
        }
        __syncthreads();
        stage = (stage + 1 >= NSTAGE) ? 0 : stage + 1;
    }

    float* dstb = (kh == 0) ? out : g_po;
    const int qr = lane >> 2;
    const int qc = lane & 3;
#pragma unroll
    for (int mt = 0; mt < 4; ++mt) {
#pragma unroll
        for (int nt = 0; nt < 4; ++nt) {
            const int o = m0 + wm + mt * 16 + qr;
            const int p = n0 + wn + nt * 8 + 2 * qc;
            float* o0 = dstb + ((size_t)(b * CO + o)) * HW + p;
            float2 v0; v0.x = c[mt * 4 + nt][0]; v0.y = c[mt * 4 + nt][1];
            *(float2*)o0 = v0;
            float2 v1; v1.x = c[mt * 4 + nt][2]; v1.y = c[mt * 4 + nt][3];
            *(float2*)(o0 + 8 * HW) = v1;
        }
    }
}

// ---------------------------------------------------------------------------
// Kernel 4: split-K reduce  out += g_po   (float4)
// ---------------------------------------------------------------------------
__global__ __launch_bounds__(256)
void reduce_kernel(float* __restrict__ out)
{
    const int i = blockIdx.x * 256 + threadIdx.x;    // BATCH*CO*HW/4 = 524288
    float4 a = ((float4*)out)[i];
    const float4 p = ((const float4*)g_po)[i];
    a.x += p.x; a.y += p.y; a.z += p.z; a.w += p.w;
    ((float4*)out)[i] = a;
}

// ---------------------------------------------------------------------------
extern "C" void kernel_launch(void* const* d_in, const int* in_sizes, int n_in,
                              void* d_out, int out_size)
{
    const float* x   = (const float*)d_in[0];   // [2,256,64,64]
    const float* res = (const float*)d_in[1];   // [2,256,64,64]
    const float* ow  = (const float*)d_in[2];   // [18,256,3,3]
    const float* ob  = (const float*)d_in[3];   // [18]
    const float* mw  = (const float*)d_in[4];   // [9,256,3,3]
    const float* mb  = (const float*)d_in[5];   // [9]
    const float* rw  = (const float*)d_in[6];   // [256,256,3,3]
    float* out = (float*)d_out;                 // [2,256,64,64]

    static int smem_set = 0;
    if (!smem_set) {
        cudaFuncSetAttribute(gemm_mma_kernel,
                             cudaFuncAttributeMaxDynamicSharedMemorySize, GEMM_SMEM);
        smem_set = 1;
    }

    conv_offmod_kernel<<<400, 128>>>(x, res, ow, mw, rw);
    sample_kernel<<<dim3(HW / 64, 2, BATCH), 288>>>(x, ob, mb);
    gemm_mma_kernel<<<dim3(HW / 128, CO / 128, BATCH * 2), 256, GEMM_SMEM>>>(out);
    reduce_kernel<<<BATCH * CO * HW / 4 / 256, 256>>>(out);
}